// round 12
// baseline (speedup 1.0000x reference)
#include <cuda_runtime.h>
#include <cuda_fp16.h>
#include <math.h>

// ---------------- problem constants ----------------
#define BS    32
#define LQ    300
#define NH    8
#define HD    32
#define EMB   (NH*HD)        // 256
#define NLVL  4
#define NPTS  4
#define SUMP  (NLVL*NPTS)    // 16
#define TOTAL 8500
#define MROWS (BS*LQ)        // 9600
#define NPOINT ((size_t)BS*NH*LQ*SUMP)   // 1,228,800

#define TS    96                          // transpose tile width (s)
#define STILES ((TOTAL + TS - 1) / TS)    // 89
#define NTB   (STILES * BS * NH)          // 22784 transpose blocks
#define NPB   (MROWS / 32)                // 300 proj blocks
#define NCB   (NTB + NPB)                 // 23084 combined blocks

__device__ __constant__ int c_lvl_start[NLVL] = {0, 6400, 8000, 8400};
__device__ __constant__ int c_lvl_H[NLVL]     = {80, 40, 20, 10};
__device__ __constant__ int c_lvl_W[NLVL]     = {80, 40, 20, 10};

// ---------------- scratch ----------------
__device__ __half   g_valueT[(size_t)BS*NH*TOTAL*HD]; // ~139 MB, [b,h,s,d] fp16
__device__ ushort4  g_midx[NPOINT];                   // [bh][q][p] 4 clamped tap indices (16-bit)
__device__ float4   g_mw[NPOINT];                     // [bh][q][p] 4 attn-premult bilinear weights

// ---------------- f32x2 packed helpers (sm_103a) ----------------
typedef unsigned long long ull;
__device__ __forceinline__ ull pack2(float lo, float hi) {
    ull r; asm("mov.b64 %0, {%1, %2};" : "=l"(r) : "f"(lo), "f"(hi)); return r;
}
__device__ __forceinline__ void unpack2(ull v, float& lo, float& hi) {
    asm("mov.b64 {%0, %1}, %2;" : "=f"(lo), "=f"(hi) : "l"(v));
}
__device__ __forceinline__ void ffma2(ull& d, ull a, ull b) {
    asm("fma.rn.f32x2 %0, %1, %2, %0;" : "+l"(d) : "l"(a), "l"(b));
}
__device__ __forceinline__ void fadd2(ull& d, ull a) {
    asm("add.rn.f32x2 %0, %0, %1;" : "+l"(d) : "l"(a));
}

// ================= combined kernel: transpose blocks + proj blocks =================
// 384 threads. Block role by blockIdx.x:
//   bid < 600 and even  -> proj block  pidx = bid/2        (300 blocks, all start in the first waves)
//   bid < 600 and odd   -> transpose tile tidx = bid/2
//   bid >= 600          -> transpose tile tidx = bid - 300
// Wave 1 = ~148 proj + ~148 transpose -> 1 P + 1 T block per SM (co-resident).
__global__ __launch_bounds__(384, 2) void k_combined(const float* __restrict__ value,
                                                     const float* __restrict__ query,
                                                     const float* __restrict__ refpts,
                                                     const float* __restrict__ W_off,
                                                     const float* __restrict__ b_off,
                                                     const float* __restrict__ W_attn,
                                                     const float* __restrict__ b_attn) {
    // shared memory union: proj uses qs(36864B)+attn(16384B); transpose uses tile(12800B)
    __shared__ __align__(16) char smbuf[EMB * 36 * 4 + 32 * 128 * 4];
    int bid = blockIdx.x;
    int t   = threadIdx.x;

    bool isP;
    int pidx = 0, tidx;
    if (bid < 600) {
        isP  = ((bid & 1) == 0);
        pidx = bid >> 1;
        tidx = bid >> 1;
    } else {
        isP  = false;
        tidx = bid - NPB;
    }

    if (!isP) {
        // ---------------- transpose tile: 32 d x 96 s ----------------
        float* tile = (float*)smbuf;       // [32][100]
        int bh = tidx / STILES;
        int s0 = (tidx % STILES) * TS;

        const float* src = value + (size_t)bh * HD * TOTAL;
        __half* dst = g_valueT + (size_t)bh * TOTAL * HD;

        int sx4 = t % 24;                  // float4 index along s (24*4 = 96)
        int dh  = t / 24;                  // 0..15
        int sbase = s0 + sx4 * 4;
        bool full = (s0 + TS <= TOTAL);

        if (dh < 16) {
            #pragma unroll
            for (int i = 0; i < 2; i++) {
                int d = dh + i * 16;
                float4 v;
                if (full || sbase + 3 < TOTAL) {
                    v = *(const float4*)(src + (size_t)d * TOTAL + sbase);
                } else {
                    v.x = (sbase + 0 < TOTAL) ? src[(size_t)d * TOTAL + sbase + 0] : 0.f;
                    v.y = (sbase + 1 < TOTAL) ? src[(size_t)d * TOTAL + sbase + 1] : 0.f;
                    v.z = (sbase + 2 < TOTAL) ? src[(size_t)d * TOTAL + sbase + 2] : 0.f;
                    v.w = (sbase + 3 < TOTAL) ? src[(size_t)d * TOTAL + sbase + 3] : 0.f;
                }
                *(float4*)(tile + d * 100 + sx4 * 4) = v;
            }
        }
        __syncthreads();
        // write: 96 rows x 16 half2 = 1536 entities; 4 per thread
        #pragma unroll
        for (int i = 0; i < 4; i++) {
            int e  = t + i * 384;
            int r  = e >> 4;               // local s row 0..95
            int dp = e & 15;               // d pair
            int s  = s0 + r;
            if (full || s < TOTAL) {
                float lo = tile[(2*dp)     * 100 + r];
                float hi = tile[(2*dp + 1) * 100 + r];
                *((__half2*)(dst + (size_t)s * HD) + dp) = __floats2half2_rn(lo, hi);
            }
        }
        return;
    }

    // ---------------- proj block: 32 query rows x 384 virtual cols ----------------
    float* qs     = (float*)smbuf;                    // [k][row], stride 36
    float* attn_s = (float*)(smbuf + EMB * 36 * 4);   // [row][h*16+p]
    int m0 = pidx * 32;

    for (int idx = t; idx < 32 * EMB; idx += 384) {
        int row = idx >> 8;
        int k   = idx & 255;
        qs[k * 36 + row] = query[(size_t)m0 * EMB + idx];
    }
    __syncthreads();

    int rt = t / 96;                     // 0..3
    int ct = t % 96;                     // 0..95
    bool is_off = (ct < 64);

    const float* Wp;
    int ldw;
    if (is_off) { Wp = W_off  + 4 * ct;        ldw = EMB; }
    else        { Wp = W_attn + 4 * (ct - 64); ldw = NH * SUMP; }

    ull acc[4][4];
    #pragma unroll
    for (int j = 0; j < 4; j++)
        #pragma unroll
        for (int c = 0; c < 4; c++) acc[j][c] = 0ull;

    const int roff = rt * 8;

    // W prefetch distance = 2 k-iterations
    float4 wv0 = *(const float4*)(Wp);
    float4 wv1 = *(const float4*)(Wp + ldw);

    for (int k = 0; k < EMB; k += 2) {
        float4 wn0, wn1;
        if (k + 3 < EMB) {
            wn0 = *(const float4*)(Wp + (size_t)(k + 2) * ldw);
            wn1 = *(const float4*)(Wp + (size_t)(k + 3) * ldw);
        }
        {
            ulonglong2 qa = *(const ulonglong2*)(qs + k * 36 + roff);
            ulonglong2 qb = *(const ulonglong2*)(qs + k * 36 + roff + 4);
            ull w2[4];
            w2[0] = pack2(wv0.x, wv0.x); w2[1] = pack2(wv0.y, wv0.y);
            w2[2] = pack2(wv0.z, wv0.z); w2[3] = pack2(wv0.w, wv0.w);
            #pragma unroll
            for (int c = 0; c < 4; c++) {
                ffma2(acc[0][c], qa.x, w2[c]);
                ffma2(acc[1][c], qa.y, w2[c]);
                ffma2(acc[2][c], qb.x, w2[c]);
                ffma2(acc[3][c], qb.y, w2[c]);
            }
        }
        {
            ulonglong2 qa = *(const ulonglong2*)(qs + (k + 1) * 36 + roff);
            ulonglong2 qb = *(const ulonglong2*)(qs + (k + 1) * 36 + roff + 4);
            ull w2[4];
            w2[0] = pack2(wv1.x, wv1.x); w2[1] = pack2(wv1.y, wv1.y);
            w2[2] = pack2(wv1.z, wv1.z); w2[3] = pack2(wv1.w, wv1.w);
            #pragma unroll
            for (int c = 0; c < 4; c++) {
                ffma2(acc[0][c], qa.x, w2[c]);
                ffma2(acc[1][c], qa.y, w2[c]);
                ffma2(acc[2][c], qb.x, w2[c]);
                ffma2(acc[3][c], qb.y, w2[c]);
            }
        }
        wv0 = wn0; wv1 = wn1;
    }

    float bias_[4];
    {
        const float* bp = is_off ? (b_off + 4 * ct) : (b_attn + 4 * (ct - 64));
        float4 bb = *(const float4*)bp;
        bias_[0] = bb.x; bias_[1] = bb.y; bias_[2] = bb.z; bias_[3] = bb.w;
    }

    // ---- phase A: attn threads -> softmax -> smem ----
    if (!is_off) {
        int cta = ct - 64;
        int h   = cta >> 2;
        int p0  = (4 * cta) & 15;
        #pragma unroll
        for (int j = 0; j < 4; j++) {
            #pragma unroll
            for (int par = 0; par < 2; par++) {
                int r  = roff + 2 * j + par;
                float v[4];
                float mx = -1e30f;
                #pragma unroll
                for (int c = 0; c < 4; c++) {
                    float lo, hi; unpack2(acc[j][c], lo, hi);
                    v[c] = (par ? hi : lo) + bias_[c];
                    mx = fmaxf(mx, v[c]);
                }
                mx = fmaxf(mx, __shfl_xor_sync(0xffffffffu, mx, 1));
                mx = fmaxf(mx, __shfl_xor_sync(0xffffffffu, mx, 2));
                float s = 0.f;
                #pragma unroll
                for (int c = 0; c < 4; c++) { v[c] = __expf(v[c] - mx); s += v[c]; }
                s += __shfl_xor_sync(0xffffffffu, s, 1);
                s += __shfl_xor_sync(0xffffffffu, s, 2);
                float inv = __frcp_rn(s);
                #pragma unroll
                for (int c = 0; c < 4; c++)
                    attn_s[r * 128 + h * 16 + p0 + c] = v[c] * inv;
            }
        }
    }
    __syncthreads();

    // ---- phase B: off threads -> locations -> tap meta (attn-premultiplied) ----
    if (is_off) {
        int h     = ct >> 3;
        int pbase = (2 * ct) & 15;
        int lvl   = pbase >> 2;
        int Hh = c_lvl_H[lvl], Ww = c_lvl_W[lvl];
        int st = c_lvl_start[lvl];

        #pragma unroll
        for (int j = 0; j < 4; j++) {
            #pragma unroll
            for (int par = 0; par < 2; par++) {
                int r  = roff + 2 * j + par;
                int gm = m0 + r;
                int b  = gm / LQ;
                int q  = gm - b * LQ;
                float4 rp = __ldg((const float4*)refpts + gm);
                size_t obase = ((size_t)(b * NH + h) * LQ + q) * SUMP + pbase;
                #pragma unroll
                for (int pt = 0; pt < 2; pt++) {
                    float lo0, hi0, lo1, hi1;
                    unpack2(acc[j][2*pt],     lo0, hi0);
                    unpack2(acc[j][2*pt + 1], lo1, hi1);
                    float vx = (par ? hi0 : lo0) + bias_[2*pt];
                    float vy = (par ? hi1 : lo1) + bias_[2*pt + 1];
                    float locx = fmaf(vx * 0.125f, rp.z, rp.x);
                    float locy = fmaf(vy * 0.125f, rp.w, rp.y);

                    float x = locx * (float)Ww - 0.5f;
                    float y = locy * (float)Hh - 0.5f;
                    float fx0 = floorf(x), fy0 = floorf(y);
                    int ix0 = (int)fx0, iy0 = (int)fy0;
                    float fx = x - fx0, fy = y - fy0;
                    int ix1 = ix0 + 1, iy1 = iy0 + 1;

                    bool vx0 = (ix0 >= 0) & (ix0 < Ww);
                    bool vx1 = (ix1 >= 0) & (ix1 < Ww);
                    bool vy0 = (iy0 >= 0) & (iy0 < Hh);
                    bool vy1 = (iy1 >= 0) & (iy1 < Hh);

                    int cx0 = min(max(ix0, 0), Ww - 1);
                    int cx1 = min(max(ix1, 0), Ww - 1);
                    int cy0 = min(max(iy0, 0), Hh - 1);
                    int cy1 = min(max(iy1, 0), Hh - 1);

                    float a = attn_s[r * 128 + h * 16 + pbase + pt];

                    ushort4 idx;
                    idx.x = (unsigned short)(st + cy0 * Ww + cx0);
                    idx.y = (unsigned short)(st + cy0 * Ww + cx1);
                    idx.z = (unsigned short)(st + cy1 * Ww + cx0);
                    idx.w = (unsigned short)(st + cy1 * Ww + cx1);

                    float4 w4;
                    w4.x = (vx0 & vy0) ? a * (1.f - fx) * (1.f - fy) : 0.f;
                    w4.y = (vx1 & vy0) ? a * fx * (1.f - fy)         : 0.f;
                    w4.z = (vx0 & vy1) ? a * (1.f - fx) * fy         : 0.f;
                    w4.w = (vx1 & vy1) ? a * fx * fy                 : 0.f;

                    g_midx[obase + pt] = idx;
                    g_mw[obase + pt]   = w4;
                }
            }
        }
    }
}

// ================= kernel 3: bilinear sampling + weighted sum =================
// Warp = 8 queries; 4 lanes per query; lane = 8 channels (LDG.128 taps).
#define QOCT ((LQ + 7) / 8)   // 38
__global__ __launch_bounds__(256) void k_sample(float* __restrict__ out) {
    int wq = blockIdx.x * 8 + (threadIdx.x >> 5);   // < 9728
    int lane = threadIdx.x & 31;
    int qi = lane >> 2;       // query sub-index in octet
    int l  = lane & 3;        // channel octet index (channels 8l..8l+7)

    int oct = wq % QOCT;
    int bh  = wq / QOCT;
    int q   = oct * 8 + qi;
    bool valid = (q < LQ);
    int qc = valid ? q : (LQ - 1);
    int b = bh >> 3;
    int h = bh & 7;

    size_t base = ((size_t)bh * LQ + qc) * SUMP;
    const uint2*  __restrict__ mi2 = (const uint2*)(g_midx + base);
    const float4* __restrict__ mw  = g_mw + base;
    const float4* __restrict__ vt16 =
        (const float4*)(g_valueT + (size_t)bh * TOTAL * HD);  // 16B = 8 channels

    ull acc0 = 0ull, acc1 = 0ull, acc2v = 0ull, acc3 = 0ull;

    #pragma unroll
    for (int p = 0; p < SUMP; p++) {
        uint2  u = __ldg(mi2 + p);
        float4 w = __ldg(mw + p);
        int i00 = u.x & 0xFFFF;
        int i10 = u.x >> 16;
        int i01 = u.y & 0xFFFF;
        int i11 = u.y >> 16;

        __half2 z = __float2half2_rn(0.f);
        __half2 bl0 = z, bl1 = z, bl2 = z, bl3 = z;

        {
            float4 v = __ldg(vt16 + (size_t)i00 * 4 + l);
            const __half2* vh = (const __half2*)&v;
            __half2 wh = __float2half2_rn(w.x);
            bl0 = __hfma2(vh[0], wh, bl0); bl1 = __hfma2(vh[1], wh, bl1);
            bl2 = __hfma2(vh[2], wh, bl2); bl3 = __hfma2(vh[3], wh, bl3);
        }
        {
            float4 v = __ldg(vt16 + (size_t)i10 * 4 + l);
            const __half2* vh = (const __half2*)&v;
            __half2 wh = __float2half2_rn(w.y);
            bl0 = __hfma2(vh[0], wh, bl0); bl1 = __hfma2(vh[1], wh, bl1);
            bl2 = __hfma2(vh[2], wh, bl2); bl3 = __hfma2(vh[3], wh, bl3);
        }
        {
            float4 v = __ldg(vt16 + (size_t)i01 * 4 + l);
            const __half2* vh = (const __half2*)&v;
            __half2 wh = __float2half2_rn(w.z);
            bl0 = __hfma2(vh[0], wh, bl0); bl1 = __hfma2(vh[1], wh, bl1);
            bl2 = __hfma2(vh[2], wh, bl2); bl3 = __hfma2(vh[3], wh, bl3);
        }
        {
            float4 v = __ldg(vt16 + (size_t)i11 * 4 + l);
            const __half2* vh = (const __half2*)&v;
            __half2 wh = __float2half2_rn(w.w);
            bl0 = __hfma2(vh[0], wh, bl0); bl1 = __hfma2(vh[1], wh, bl1);
            bl2 = __hfma2(vh[2], wh, bl2); bl3 = __hfma2(vh[3], wh, bl3);
        }

        float2 f0 = __half22float2(bl0);
        float2 f1 = __half22float2(bl1);
        float2 f2 = __half22float2(bl2);
        float2 f3 = __half22float2(bl3);
        fadd2(acc0, pack2(f0.x, f0.y));
        fadd2(acc1, pack2(f1.x, f1.y));
        fadd2(acc2v, pack2(f2.x, f2.y));
        fadd2(acc3, pack2(f3.x, f3.y));
    }

    if (valid) {
        float o0,o1,o2,o3,o4,o5,o6,o7;
        unpack2(acc0, o0, o1);
        unpack2(acc1, o2, o3);
        unpack2(acc2v, o4, o5);
        unpack2(acc3, o6, o7);
        float* op = out + ((size_t)b * LQ + q) * EMB + h * HD + 8 * l;
        *(float4*)(op)     = make_float4(o0, o1, o2, o3);
        *(float4*)(op + 4) = make_float4(o4, o5, o6, o7);
    }
}

// ================= launch =================
// Single stream: combined (transpose+proj block-mixed) -> sample.
extern "C" void kernel_launch(void* const* d_in, const int* in_sizes, int n_in,
                              void* d_out, int out_size) {
    const float* query  = (const float*)d_in[0];
    const float* refpts = (const float*)d_in[1];
    const float* value  = (const float*)d_in[2];
    const float* W_off  = (const float*)d_in[4];
    const float* b_off  = (const float*)d_in[5];
    const float* W_attn = (const float*)d_in[6];
    const float* b_attn = (const float*)d_in[7];
    float* out = (float*)d_out;

    k_combined<<<NCB, 384>>>(value, query, refpts, W_off, b_off, W_attn, b_attn);

    int nwarps = BS * NH * QOCT;              // 9728
    k_sample<<<(nwarps + 7) / 8, 256>>>(out);
}

// round 13
// speedup vs baseline: 1.8961x; 1.8961x over previous
#include <cuda_runtime.h>
#include <cuda_fp16.h>
#include <math.h>

// ---------------- problem constants ----------------
#define BS    32
#define LQ    300
#define NH    8
#define HD    32
#define EMB   (NH*HD)        // 256
#define NLVL  4
#define NPTS  4
#define SUMP  (NLVL*NPTS)    // 16
#define TOTAL 8500
#define MROWS (BS*LQ)        // 9600
#define NPOINT ((size_t)BS*NH*LQ*SUMP)   // 1,228,800

__device__ __constant__ int c_lvl_start[NLVL] = {0, 6400, 8000, 8400};
__device__ __constant__ int c_lvl_H[NLVL]     = {80, 40, 20, 10};
__device__ __constant__ int c_lvl_W[NLVL]     = {80, 40, 20, 10};

// ---------------- scratch ----------------
__device__ __half   g_valueT[(size_t)BS*NH*TOTAL*HD]; // ~139 MB, [b,h,s,d] fp16
__device__ ushort4  g_midx[NPOINT];                   // [bh][q][p] 4 clamped tap indices (16-bit)
__device__ float4   g_mw[NPOINT];                     // [bh][q][p] 4 attn-premult bilinear weights

// ---------------- f32x2 packed helpers (sm_103a) ----------------
typedef unsigned long long ull;
__device__ __forceinline__ ull pack2(float lo, float hi) {
    ull r; asm("mov.b64 %0, {%1, %2};" : "=l"(r) : "f"(lo), "f"(hi)); return r;
}
__device__ __forceinline__ void unpack2(ull v, float& lo, float& hi) {
    asm("mov.b64 {%0, %1}, %2;" : "=f"(lo), "=f"(hi) : "l"(v));
}
__device__ __forceinline__ void ffma2(ull& d, ull a, ull b) {
    asm("fma.rn.f32x2 %0, %1, %2, %0;" : "+l"(d) : "l"(a), "l"(b));
}
__device__ __forceinline__ void fadd2(ull& d, ull a) {
    asm("add.rn.f32x2 %0, %0, %1;" : "+l"(d) : "l"(a));
}

// ================= kernel 1: value transpose fp32 [b,h,d,s] -> fp16 [b,h,s,d] =================
// 128 threads/block so a T block fits into the 4096-reg gap left by two resident
// k_proj blocks (2*384*80 = 61440; 128*~24 = 3072 <= 4096) -> true T||P co-residence.
// Tile: 64 s x 32 d. bh chunked: grid.y covers [bh0, bh0+grid.y)
__global__ __launch_bounds__(128) void k_transpose(const float* __restrict__ value, int bh0) {
    __shared__ float tile[32 * 68];
    int bh = bh0 + blockIdx.y;
    int s0 = blockIdx.x * 64;
    int t  = threadIdx.x;
    int sx4 = t & 15;                    // float4 index along s (16*4 = 64)
    int dh  = t >> 4;                    // 0..7

    const float* src = value + (size_t)bh * HD * TOTAL;
    __half* dst = g_valueT + (size_t)bh * TOTAL * HD;

    int sbase = s0 + sx4 * 4;
    #pragma unroll
    for (int i = 0; i < 4; i++) {
        int d = dh + i * 8;
        float4 v;
        if (sbase + 3 < TOTAL) {
            v = *(const float4*)(src + (size_t)d * TOTAL + sbase);
        } else {
            v.x = (sbase + 0 < TOTAL) ? src[(size_t)d * TOTAL + sbase + 0] : 0.f;
            v.y = (sbase + 1 < TOTAL) ? src[(size_t)d * TOTAL + sbase + 1] : 0.f;
            v.z = (sbase + 2 < TOTAL) ? src[(size_t)d * TOTAL + sbase + 2] : 0.f;
            v.w = (sbase + 3 < TOTAL) ? src[(size_t)d * TOTAL + sbase + 3] : 0.f;
        }
        *(float4*)(tile + d * 68 + sx4 * 4) = v;
    }
    __syncthreads();
    // write: 64 rows x 16 half2 entities = 1024; 8 per thread
    #pragma unroll
    for (int i = 0; i < 8; i++) {
        int e  = t + i * 128;
        int r  = e >> 4;                 // local s row 0..63
        int dp = e & 15;                 // d pair
        int s  = s0 + r;
        if (s < TOTAL) {
            float lo = tile[(2*dp)     * 68 + r];
            float hi = tile[(2*dp + 1) * 68 + r];
            *((__half2*)(dst + (size_t)s * HD) + dp) = __floats2half2_rn(lo, hi);
        }
    }
}

// ================= kernel 2: fused projections + softmax + tap meta (attn premult) =================
// Block = 32 query rows, 384 threads (300 blocks). rt = t/96 (0..3) -> rows rt*8..+7;
// ct = t%96 -> cols 4ct..4ct+3 of virtual [W_off | W_attn]. Warps uniform in matrix type.
__global__ __launch_bounds__(384, 2) void k_proj(const float* __restrict__ query,
                                                 const float* __restrict__ refpts,
                                                 const float* __restrict__ W_off,
                                                 const float* __restrict__ b_off,
                                                 const float* __restrict__ W_attn,
                                                 const float* __restrict__ b_attn) {
    __shared__ float qs[EMB * 36];       // [k][row], stride 36 (144B, 16B-aligned)
    __shared__ float attn_s[32 * 128];   // [row][h*16+p]
    int m0 = blockIdx.x * 32;
    int t  = threadIdx.x;

    for (int idx = t; idx < 32 * EMB; idx += 384) {
        int row = idx >> 8;
        int k   = idx & 255;
        qs[k * 36 + row] = query[(size_t)m0 * EMB + idx];
    }
    __syncthreads();

    int rt = t / 96;                     // 0..3
    int ct = t % 96;                     // 0..95
    bool is_off = (ct < 64);

    const float* Wp;
    int ldw;
    if (is_off) { Wp = W_off  + 4 * ct;        ldw = EMB; }
    else        { Wp = W_attn + 4 * (ct - 64); ldw = NH * SUMP; }

    ull acc[4][4];
    #pragma unroll
    for (int j = 0; j < 4; j++)
        #pragma unroll
        for (int c = 0; c < 4; c++) acc[j][c] = 0ull;

    const int roff = rt * 8;

    // W prefetch distance = 2 k-iterations (covers L2 hit latency)
    float4 wv0 = *(const float4*)(Wp);
    float4 wv1 = *(const float4*)(Wp + ldw);

    for (int k = 0; k < EMB; k += 2) {
        float4 wn0, wn1;
        if (k + 3 < EMB) {
            wn0 = *(const float4*)(Wp + (size_t)(k + 2) * ldw);
            wn1 = *(const float4*)(Wp + (size_t)(k + 3) * ldw);
        }
        {
            ulonglong2 qa = *(const ulonglong2*)(qs + k * 36 + roff);
            ulonglong2 qb = *(const ulonglong2*)(qs + k * 36 + roff + 4);
            ull w2[4];
            w2[0] = pack2(wv0.x, wv0.x); w2[1] = pack2(wv0.y, wv0.y);
            w2[2] = pack2(wv0.z, wv0.z); w2[3] = pack2(wv0.w, wv0.w);
            #pragma unroll
            for (int c = 0; c < 4; c++) {
                ffma2(acc[0][c], qa.x, w2[c]);
                ffma2(acc[1][c], qa.y, w2[c]);
                ffma2(acc[2][c], qb.x, w2[c]);
                ffma2(acc[3][c], qb.y, w2[c]);
            }
        }
        {
            ulonglong2 qa = *(const ulonglong2*)(qs + (k + 1) * 36 + roff);
            ulonglong2 qb = *(const ulonglong2*)(qs + (k + 1) * 36 + roff + 4);
            ull w2[4];
            w2[0] = pack2(wv1.x, wv1.x); w2[1] = pack2(wv1.y, wv1.y);
            w2[2] = pack2(wv1.z, wv1.z); w2[3] = pack2(wv1.w, wv1.w);
            #pragma unroll
            for (int c = 0; c < 4; c++) {
                ffma2(acc[0][c], qa.x, w2[c]);
                ffma2(acc[1][c], qa.y, w2[c]);
                ffma2(acc[2][c], qb.x, w2[c]);
                ffma2(acc[3][c], qb.y, w2[c]);
            }
        }
        wv0 = wn0; wv1 = wn1;
    }

    float bias_[4];
    {
        const float* bp = is_off ? (b_off + 4 * ct) : (b_attn + 4 * (ct - 64));
        float4 bb = *(const float4*)bp;
        bias_[0] = bb.x; bias_[1] = bb.y; bias_[2] = bb.z; bias_[3] = bb.w;
    }

    // ---- phase A: attn threads -> softmax -> smem ----
    if (!is_off) {
        int cta = ct - 64;
        int h   = cta >> 2;
        int p0  = (4 * cta) & 15;
        #pragma unroll
        for (int j = 0; j < 4; j++) {
            #pragma unroll
            for (int par = 0; par < 2; par++) {
                int r  = roff + 2 * j + par;
                float v[4];
                float mx = -1e30f;
                #pragma unroll
                for (int c = 0; c < 4; c++) {
                    float lo, hi; unpack2(acc[j][c], lo, hi);
                    v[c] = (par ? hi : lo) + bias_[c];
                    mx = fmaxf(mx, v[c]);
                }
                mx = fmaxf(mx, __shfl_xor_sync(0xffffffffu, mx, 1));
                mx = fmaxf(mx, __shfl_xor_sync(0xffffffffu, mx, 2));
                float s = 0.f;
                #pragma unroll
                for (int c = 0; c < 4; c++) { v[c] = __expf(v[c] - mx); s += v[c]; }
                s += __shfl_xor_sync(0xffffffffu, s, 1);
                s += __shfl_xor_sync(0xffffffffu, s, 2);
                float inv = __frcp_rn(s);
                #pragma unroll
                for (int c = 0; c < 4; c++)
                    attn_s[r * 128 + h * 16 + p0 + c] = v[c] * inv;
            }
        }
    }
    __syncthreads();

    // ---- phase B: off threads -> locations -> tap meta (attn-premultiplied) ----
    if (is_off) {
        int h     = ct >> 3;
        int pbase = (2 * ct) & 15;
        int lvl   = pbase >> 2;
        int Hh = c_lvl_H[lvl], Ww = c_lvl_W[lvl];
        int st = c_lvl_start[lvl];

        #pragma unroll
        for (int j = 0; j < 4; j++) {
            #pragma unroll
            for (int par = 0; par < 2; par++) {
                int r  = roff + 2 * j + par;
                int gm = m0 + r;
                int b  = gm / LQ;
                int q  = gm - b * LQ;
                float4 rp = __ldg((const float4*)refpts + gm);
                size_t obase = ((size_t)(b * NH + h) * LQ + q) * SUMP + pbase;
                #pragma unroll
                for (int pt = 0; pt < 2; pt++) {
                    float lo0, hi0, lo1, hi1;
                    unpack2(acc[j][2*pt],     lo0, hi0);
                    unpack2(acc[j][2*pt + 1], lo1, hi1);
                    float vx = (par ? hi0 : lo0) + bias_[2*pt];
                    float vy = (par ? hi1 : lo1) + bias_[2*pt + 1];
                    float locx = fmaf(vx * 0.125f, rp.z, rp.x);
                    float locy = fmaf(vy * 0.125f, rp.w, rp.y);

                    float x = locx * (float)Ww - 0.5f;
                    float y = locy * (float)Hh - 0.5f;
                    float fx0 = floorf(x), fy0 = floorf(y);
                    int ix0 = (int)fx0, iy0 = (int)fy0;
                    float fx = x - fx0, fy = y - fy0;
                    int ix1 = ix0 + 1, iy1 = iy0 + 1;

                    bool vx0 = (ix0 >= 0) & (ix0 < Ww);
                    bool vx1 = (ix1 >= 0) & (ix1 < Ww);
                    bool vy0 = (iy0 >= 0) & (iy0 < Hh);
                    bool vy1 = (iy1 >= 0) & (iy1 < Hh);

                    int cx0 = min(max(ix0, 0), Ww - 1);
                    int cx1 = min(max(ix1, 0), Ww - 1);
                    int cy0 = min(max(iy0, 0), Hh - 1);
                    int cy1 = min(max(iy1, 0), Hh - 1);

                    float a = attn_s[r * 128 + h * 16 + pbase + pt];

                    ushort4 idx;
                    idx.x = (unsigned short)(st + cy0 * Ww + cx0);
                    idx.y = (unsigned short)(st + cy0 * Ww + cx1);
                    idx.z = (unsigned short)(st + cy1 * Ww + cx0);
                    idx.w = (unsigned short)(st + cy1 * Ww + cx1);

                    float4 w4;
                    w4.x = (vx0 & vy0) ? a * (1.f - fx) * (1.f - fy) : 0.f;
                    w4.y = (vx1 & vy0) ? a * fx * (1.f - fy)         : 0.f;
                    w4.z = (vx0 & vy1) ? a * (1.f - fx) * fy         : 0.f;
                    w4.w = (vx1 & vy1) ? a * fx * fy                 : 0.f;

                    g_midx[obase + pt] = idx;
                    g_mw[obase + pt]   = w4;
                }
            }
        }
    }
}

// ================= kernel 3: bilinear sampling + weighted sum =================
// Warp = 8 queries; 4 lanes per query; lane = 8 channels (LDG.128 taps).
// bh chunked: covers [bh0, ...)
#define QOCT ((LQ + 7) / 8)   // 38
__global__ __launch_bounds__(256) void k_sample(float* __restrict__ out, int bh0) {
    int wq = blockIdx.x * 8 + (threadIdx.x >> 5);
    int lane = threadIdx.x & 31;
    int qi = lane >> 2;       // query sub-index in octet
    int l  = lane & 3;        // channel octet index (channels 8l..8l+7)

    int oct = wq % QOCT;
    int bh  = bh0 + wq / QOCT;
    int q   = oct * 8 + qi;
    bool valid = (q < LQ);
    int qc = valid ? q : (LQ - 1);
    int b = bh >> 3;
    int h = bh & 7;

    size_t base = ((size_t)bh * LQ + qc) * SUMP;
    const uint2*  __restrict__ mi2 = (const uint2*)(g_midx + base);
    const float4* __restrict__ mw  = g_mw + base;
    const float4* __restrict__ vt16 =
        (const float4*)(g_valueT + (size_t)bh * TOTAL * HD);  // 16B = 8 channels

    ull acc0 = 0ull, acc1 = 0ull, acc2v = 0ull, acc3 = 0ull;

    #pragma unroll
    for (int p = 0; p < SUMP; p++) {
        uint2  u = __ldg(mi2 + p);
        float4 w = __ldg(mw + p);
        int i00 = u.x & 0xFFFF;
        int i10 = u.x >> 16;
        int i01 = u.y & 0xFFFF;
        int i11 = u.y >> 16;

        __half2 z = __float2half2_rn(0.f);
        __half2 bl0 = z, bl1 = z, bl2 = z, bl3 = z;

        {
            float4 v = __ldg(vt16 + (size_t)i00 * 4 + l);
            const __half2* vh = (const __half2*)&v;
            __half2 wh = __float2half2_rn(w.x);
            bl0 = __hfma2(vh[0], wh, bl0); bl1 = __hfma2(vh[1], wh, bl1);
            bl2 = __hfma2(vh[2], wh, bl2); bl3 = __hfma2(vh[3], wh, bl3);
        }
        {
            float4 v = __ldg(vt16 + (size_t)i10 * 4 + l);
            const __half2* vh = (const __half2*)&v;
            __half2 wh = __float2half2_rn(w.y);
            bl0 = __hfma2(vh[0], wh, bl0); bl1 = __hfma2(vh[1], wh, bl1);
            bl2 = __hfma2(vh[2], wh, bl2); bl3 = __hfma2(vh[3], wh, bl3);
        }
        {
            float4 v = __ldg(vt16 + (size_t)i01 * 4 + l);
            const __half2* vh = (const __half2*)&v;
            __half2 wh = __float2half2_rn(w.z);
            bl0 = __hfma2(vh[0], wh, bl0); bl1 = __hfma2(vh[1], wh, bl1);
            bl2 = __hfma2(vh[2], wh, bl2); bl3 = __hfma2(vh[3], wh, bl3);
        }
        {
            float4 v = __ldg(vt16 + (size_t)i11 * 4 + l);
            const __half2* vh = (const __half2*)&v;
            __half2 wh = __float2half2_rn(w.w);
            bl0 = __hfma2(vh[0], wh, bl0); bl1 = __hfma2(vh[1], wh, bl1);
            bl2 = __hfma2(vh[2], wh, bl2); bl3 = __hfma2(vh[3], wh, bl3);
        }

        float2 f0 = __half22float2(bl0);
        float2 f1 = __half22float2(bl1);
        float2 f2 = __half22float2(bl2);
        float2 f3 = __half22float2(bl3);
        fadd2(acc0, pack2(f0.x, f0.y));
        fadd2(acc1, pack2(f1.x, f1.y));
        fadd2(acc2v, pack2(f2.x, f2.y));
        fadd2(acc3, pack2(f3.x, f3.y));
    }

    if (valid) {
        float o0,o1,o2,o3,o4,o5,o6,o7;
        unpack2(acc0, o0, o1);
        unpack2(acc1, o2, o3);
        unpack2(acc2v, o4, o5);
        unpack2(acc3, o6, o7);
        float* op = out + ((size_t)b * LQ + q) * EMB + h * HD + 8 * l;
        *(float4*)(op)     = make_float4(o0, o1, o2, o3);
        *(float4*)(op + 4) = make_float4(o4, o5, o6, o7);
    }
}

// ================= launch =================
// Pipelined DAG (bh halves):
//   main: Ta -> (rec eTa) Tb -> (wait eP) Sb -> (wait eSa)
//   side: (wait eFork) P -> (rec eP) -> (wait eTa) Sa -> (rec eSa)
// Stream/events are host objects (no device allocation); leaked intentionally
// (destroying capture-participating streams would invalidate the capture).
extern "C" void kernel_launch(void* const* d_in, const int* in_sizes, int n_in,
                              void* d_out, int out_size) {
    const float* query  = (const float*)d_in[0];
    const float* refpts = (const float*)d_in[1];
    const float* value  = (const float*)d_in[2];
    const float* W_off  = (const float*)d_in[4];
    const float* b_off  = (const float*)d_in[5];
    const float* W_attn = (const float*)d_in[6];
    const float* b_attn = (const float*)d_in[7];
    float* out = (float*)d_out;

    cudaStream_t s2;
    cudaEvent_t eFork, eTa, eP, eSa;
    cudaStreamCreateWithFlags(&s2, cudaStreamNonBlocking);
    cudaEventCreateWithFlags(&eFork, cudaEventDisableTiming);
    cudaEventCreateWithFlags(&eTa,   cudaEventDisableTiming);
    cudaEventCreateWithFlags(&eP,    cudaEventDisableTiming);
    cudaEventCreateWithFlags(&eSa,   cudaEventDisableTiming);

    const int NBH_HALF = (BS * NH) / 2;               // 128
    dim3 tgrid((TOTAL + 63) / 64, NBH_HALF);
    int swarps = NBH_HALF * QOCT;                     // 4864
    int sblocks = (swarps + 7) / 8;                   // 608

    // fork side stream off main
    cudaEventRecord(eFork, 0);
    cudaStreamWaitEvent(s2, eFork, 0);

    // side: proj
    k_proj<<<MROWS / 32, 384, 0, s2>>>(query, refpts, W_off, b_off, W_attn, b_attn);
    cudaEventRecord(eP, s2);

    // main: transpose first half, mark eTa
    k_transpose<<<tgrid, 128>>>(value, 0);
    cudaEventRecord(eTa, 0);

    // main: transpose second half
    k_transpose<<<tgrid, 128>>>(value, NBH_HALF);

    // side: sample first half (deps: P [program order] + Ta [event])
    cudaStreamWaitEvent(s2, eTa, 0);
    k_sample<<<sblocks, 256, 0, s2>>>(out, 0);
    cudaEventRecord(eSa, s2);

    // main: sample second half (deps: Tb [program order] + P [event])
    cudaStreamWaitEvent(0, eP, 0);
    k_sample<<<sblocks, 256>>>(out, NBH_HALF);

    // join side back into main so the captured graph is fully connected
    cudaStreamWaitEvent(0, eSa, 0);
}

// round 14
// speedup vs baseline: 1.9486x; 1.0277x over previous
#include <cuda_runtime.h>
#include <cuda_fp16.h>
#include <math.h>

// ---------------- problem constants ----------------
#define BS    32
#define LQ    300
#define NH    8
#define HD    32
#define EMB   (NH*HD)        // 256
#define NLVL  4
#define NPTS  4
#define SUMP  (NLVL*NPTS)    // 16
#define TOTAL 8500
#define MROWS (BS*LQ)        // 9600
#define NPOINT ((size_t)BS*NH*LQ*SUMP)   // 1,228,800

__device__ __constant__ int c_lvl_start[NLVL] = {0, 6400, 8000, 8400};
__device__ __constant__ int c_lvl_H[NLVL]     = {80, 40, 20, 10};
__device__ __constant__ int c_lvl_W[NLVL]     = {80, 40, 20, 10};

// ---------------- scratch ----------------
__device__ __half   g_valueT[(size_t)BS*NH*TOTAL*HD]; // ~139 MB, [b,h,s,d] fp16
__device__ ushort4  g_midx[NPOINT];                   // [bh][q][p] 4 clamped tap indices (16-bit)
__device__ float4   g_mw[NPOINT];                     // [bh][q][p] 4 attn-premult bilinear weights

// ---------------- f32x2 packed helpers (sm_103a) ----------------
typedef unsigned long long ull;
__device__ __forceinline__ ull pack2(float lo, float hi) {
    ull r; asm("mov.b64 %0, {%1, %2};" : "=l"(r) : "f"(lo), "f"(hi)); return r;
}
__device__ __forceinline__ void unpack2(ull v, float& lo, float& hi) {
    asm("mov.b64 {%0, %1}, %2;" : "=f"(lo), "=f"(hi) : "l"(v));
}
__device__ __forceinline__ void ffma2(ull& d, ull a, ull b) {
    asm("fma.rn.f32x2 %0, %1, %2, %0;" : "+l"(d) : "l"(a), "l"(b));
}
__device__ __forceinline__ void fadd2(ull& d, ull a) {
    asm("add.rn.f32x2 %0, %0, %1;" : "+l"(d) : "l"(a));
}

// ================= kernel 1: value transpose fp32 [b,h,d,s] -> fp16 [b,h,s,d] =================
// 256 threads, tile 64 s x 32 d (proven 82us shape). bh chunked via bh0.
__global__ __launch_bounds__(256) void k_transpose(const float* __restrict__ value, int bh0) {
    __shared__ float tile[32 * 68];
    int bh = bh0 + blockIdx.y;
    int s0 = blockIdx.x * 64;
    int t  = threadIdx.x;
    int sx4 = t & 15;
    int dh  = t >> 4;

    const float* src = value + (size_t)bh * HD * TOTAL;
    __half* dst = g_valueT + (size_t)bh * TOTAL * HD;

    int sbase = s0 + sx4 * 4;
    #pragma unroll
    for (int i = 0; i < 2; i++) {
        int d = dh + i * 16;
        float4 v;
        if (sbase + 3 < TOTAL) {
            v = *(const float4*)(src + (size_t)d * TOTAL + sbase);
        } else {
            v.x = (sbase + 0 < TOTAL) ? src[(size_t)d * TOTAL + sbase + 0] : 0.f;
            v.y = (sbase + 1 < TOTAL) ? src[(size_t)d * TOTAL + sbase + 1] : 0.f;
            v.z = (sbase + 2 < TOTAL) ? src[(size_t)d * TOTAL + sbase + 2] : 0.f;
            v.w = (sbase + 3 < TOTAL) ? src[(size_t)d * TOTAL + sbase + 3] : 0.f;
        }
        *(float4*)(tile + d * 68 + sx4 * 4) = v;
    }
    __syncthreads();
    #pragma unroll
    for (int i = 0; i < 4; i++) {
        int e  = t + i * 256;
        int r  = e >> 4;
        int dp = e & 15;
        int s  = s0 + r;
        if (s < TOTAL) {
            float lo = tile[(2*dp)     * 68 + r];
            float hi = tile[(2*dp + 1) * 68 + r];
            *((__half2*)(dst + (size_t)s * HD) + dp) = __floats2half2_rn(lo, hi);
        }
    }
}

// ================= kernel 2: fused projections + softmax + tap meta (attn premult) =================
// Block = 32 query rows, 384 threads (300 blocks). rt = t/96 (0..3) -> rows rt*8..+7;
// ct = t%96 -> cols 4ct..4ct+3 of virtual [W_off | W_attn]. Warps uniform in matrix type.
__global__ __launch_bounds__(384, 2) void k_proj(const float* __restrict__ query,
                                                 const float* __restrict__ refpts,
                                                 const float* __restrict__ W_off,
                                                 const float* __restrict__ b_off,
                                                 const float* __restrict__ W_attn,
                                                 const float* __restrict__ b_attn) {
    __shared__ float qs[EMB * 36];       // [k][row], stride 36 (144B, 16B-aligned)
    __shared__ float attn_s[32 * 128];   // [row][h*16+p]
    int m0 = blockIdx.x * 32;
    int t  = threadIdx.x;

    for (int idx = t; idx < 32 * EMB; idx += 384) {
        int row = idx >> 8;
        int k   = idx & 255;
        qs[k * 36 + row] = query[(size_t)m0 * EMB + idx];
    }
    __syncthreads();

    int rt = t / 96;                     // 0..3
    int ct = t % 96;                     // 0..95
    bool is_off = (ct < 64);

    const float* Wp;
    int ldw;
    if (is_off) { Wp = W_off  + 4 * ct;        ldw = EMB; }
    else        { Wp = W_attn + 4 * (ct - 64); ldw = NH * SUMP; }

    ull acc[4][4];
    #pragma unroll
    for (int j = 0; j < 4; j++)
        #pragma unroll
        for (int c = 0; c < 4; c++) acc[j][c] = 0ull;

    const int roff = rt * 8;

    // W prefetch distance = 2 k-iterations (covers L2 hit latency)
    float4 wv0 = *(const float4*)(Wp);
    float4 wv1 = *(const float4*)(Wp + ldw);

    for (int k = 0; k < EMB; k += 2) {
        float4 wn0, wn1;
        if (k + 3 < EMB) {
            wn0 = *(const float4*)(Wp + (size_t)(k + 2) * ldw);
            wn1 = *(const float4*)(Wp + (size_t)(k + 3) * ldw);
        }
        {
            ulonglong2 qa = *(const ulonglong2*)(qs + k * 36 + roff);
            ulonglong2 qb = *(const ulonglong2*)(qs + k * 36 + roff + 4);
            ull w2[4];
            w2[0] = pack2(wv0.x, wv0.x); w2[1] = pack2(wv0.y, wv0.y);
            w2[2] = pack2(wv0.z, wv0.z); w2[3] = pack2(wv0.w, wv0.w);
            #pragma unroll
            for (int c = 0; c < 4; c++) {
                ffma2(acc[0][c], qa.x, w2[c]);
                ffma2(acc[1][c], qa.y, w2[c]);
                ffma2(acc[2][c], qb.x, w2[c]);
                ffma2(acc[3][c], qb.y, w2[c]);
            }
        }
        {
            ulonglong2 qa = *(const ulonglong2*)(qs + (k + 1) * 36 + roff);
            ulonglong2 qb = *(const ulonglong2*)(qs + (k + 1) * 36 + roff + 4);
            ull w2[4];
            w2[0] = pack2(wv1.x, wv1.x); w2[1] = pack2(wv1.y, wv1.y);
            w2[2] = pack2(wv1.z, wv1.z); w2[3] = pack2(wv1.w, wv1.w);
            #pragma unroll
            for (int c = 0; c < 4; c++) {
                ffma2(acc[0][c], qa.x, w2[c]);
                ffma2(acc[1][c], qa.y, w2[c]);
                ffma2(acc[2][c], qb.x, w2[c]);
                ffma2(acc[3][c], qb.y, w2[c]);
            }
        }
        wv0 = wn0; wv1 = wn1;
    }

    float bias_[4];
    {
        const float* bp = is_off ? (b_off + 4 * ct) : (b_attn + 4 * (ct - 64));
        float4 bb = *(const float4*)bp;
        bias_[0] = bb.x; bias_[1] = bb.y; bias_[2] = bb.z; bias_[3] = bb.w;
    }

    // ---- phase A: attn threads -> softmax -> smem ----
    if (!is_off) {
        int cta = ct - 64;
        int h   = cta >> 2;
        int p0  = (4 * cta) & 15;
        #pragma unroll
        for (int j = 0; j < 4; j++) {
            #pragma unroll
            for (int par = 0; par < 2; par++) {
                int r  = roff + 2 * j + par;
                float v[4];
                float mx = -1e30f;
                #pragma unroll
                for (int c = 0; c < 4; c++) {
                    float lo, hi; unpack2(acc[j][c], lo, hi);
                    v[c] = (par ? hi : lo) + bias_[c];
                    mx = fmaxf(mx, v[c]);
                }
                mx = fmaxf(mx, __shfl_xor_sync(0xffffffffu, mx, 1));
                mx = fmaxf(mx, __shfl_xor_sync(0xffffffffu, mx, 2));
                float s = 0.f;
                #pragma unroll
                for (int c = 0; c < 4; c++) { v[c] = __expf(v[c] - mx); s += v[c]; }
                s += __shfl_xor_sync(0xffffffffu, s, 1);
                s += __shfl_xor_sync(0xffffffffu, s, 2);
                float inv = __frcp_rn(s);
                #pragma unroll
                for (int c = 0; c < 4; c++)
                    attn_s[r * 128 + h * 16 + p0 + c] = v[c] * inv;
            }
        }
    }
    __syncthreads();

    // ---- phase B: off threads -> locations -> tap meta (attn-premultiplied) ----
    if (is_off) {
        int h     = ct >> 3;
        int pbase = (2 * ct) & 15;
        int lvl   = pbase >> 2;
        int Hh = c_lvl_H[lvl], Ww = c_lvl_W[lvl];
        int st = c_lvl_start[lvl];

        #pragma unroll
        for (int j = 0; j < 4; j++) {
            #pragma unroll
            for (int par = 0; par < 2; par++) {
                int r  = roff + 2 * j + par;
                int gm = m0 + r;
                int b  = gm / LQ;
                int q  = gm - b * LQ;
                float4 rp = __ldg((const float4*)refpts + gm);
                size_t obase = ((size_t)(b * NH + h) * LQ + q) * SUMP + pbase;
                #pragma unroll
                for (int pt = 0; pt < 2; pt++) {
                    float lo0, hi0, lo1, hi1;
                    unpack2(acc[j][2*pt],     lo0, hi0);
                    unpack2(acc[j][2*pt + 1], lo1, hi1);
                    float vx = (par ? hi0 : lo0) + bias_[2*pt];
                    float vy = (par ? hi1 : lo1) + bias_[2*pt + 1];
                    float locx = fmaf(vx * 0.125f, rp.z, rp.x);
                    float locy = fmaf(vy * 0.125f, rp.w, rp.y);

                    float x = locx * (float)Ww - 0.5f;
                    float y = locy * (float)Hh - 0.5f;
                    float fx0 = floorf(x), fy0 = floorf(y);
                    int ix0 = (int)fx0, iy0 = (int)fy0;
                    float fx = x - fx0, fy = y - fy0;
                    int ix1 = ix0 + 1, iy1 = iy0 + 1;

                    bool vx0 = (ix0 >= 0) & (ix0 < Ww);
                    bool vx1 = (ix1 >= 0) & (ix1 < Ww);
                    bool vy0 = (iy0 >= 0) & (iy0 < Hh);
                    bool vy1 = (iy1 >= 0) & (iy1 < Hh);

                    int cx0 = min(max(ix0, 0), Ww - 1);
                    int cx1 = min(max(ix1, 0), Ww - 1);
                    int cy0 = min(max(iy0, 0), Hh - 1);
                    int cy1 = min(max(iy1, 0), Hh - 1);

                    float a = attn_s[r * 128 + h * 16 + pbase + pt];

                    ushort4 idx;
                    idx.x = (unsigned short)(st + cy0 * Ww + cx0);
                    idx.y = (unsigned short)(st + cy0 * Ww + cx1);
                    idx.z = (unsigned short)(st + cy1 * Ww + cx0);
                    idx.w = (unsigned short)(st + cy1 * Ww + cx1);

                    float4 w4;
                    w4.x = (vx0 & vy0) ? a * (1.f - fx) * (1.f - fy) : 0.f;
                    w4.y = (vx1 & vy0) ? a * fx * (1.f - fy)         : 0.f;
                    w4.z = (vx0 & vy1) ? a * (1.f - fx) * fy         : 0.f;
                    w4.w = (vx1 & vy1) ? a * fx * fy                 : 0.f;

                    g_midx[obase + pt] = idx;
                    g_mw[obase + pt]   = w4;
                }
            }
        }
    }
}

// ================= kernel 3: bilinear sampling + weighted sum =================
// Warp = 8 queries; 4 lanes per query; lane = 8 channels (LDG.128 taps).
#define QOCT ((LQ + 7) / 8)   // 38
__global__ __launch_bounds__(256) void k_sample(float* __restrict__ out, int bh0) {
    int wq = blockIdx.x * 8 + (threadIdx.x >> 5);
    int lane = threadIdx.x & 31;
    int qi = lane >> 2;       // query sub-index in octet
    int l  = lane & 3;        // channel octet index (channels 8l..8l+7)

    int oct = wq % QOCT;
    int bh  = bh0 + wq / QOCT;
    int q   = oct * 8 + qi;
    bool valid = (q < LQ);
    int qc = valid ? q : (LQ - 1);
    int b = bh >> 3;
    int h = bh & 7;

    size_t base = ((size_t)bh * LQ + qc) * SUMP;
    const uint2*  __restrict__ mi2 = (const uint2*)(g_midx + base);
    const float4* __restrict__ mw  = g_mw + base;
    const float4* __restrict__ vt16 =
        (const float4*)(g_valueT + (size_t)bh * TOTAL * HD);  // 16B = 8 channels

    ull acc0 = 0ull, acc1 = 0ull, acc2v = 0ull, acc3 = 0ull;

    #pragma unroll
    for (int p = 0; p < SUMP; p++) {
        uint2  u = __ldg(mi2 + p);
        float4 w = __ldg(mw + p);
        int i00 = u.x & 0xFFFF;
        int i10 = u.x >> 16;
        int i01 = u.y & 0xFFFF;
        int i11 = u.y >> 16;

        __half2 z = __float2half2_rn(0.f);
        __half2 bl0 = z, bl1 = z, bl2 = z, bl3 = z;

        {
            float4 v = __ldg(vt16 + (size_t)i00 * 4 + l);
            const __half2* vh = (const __half2*)&v;
            __half2 wh = __float2half2_rn(w.x);
            bl0 = __hfma2(vh[0], wh, bl0); bl1 = __hfma2(vh[1], wh, bl1);
            bl2 = __hfma2(vh[2], wh, bl2); bl3 = __hfma2(vh[3], wh, bl3);
        }
        {
            float4 v = __ldg(vt16 + (size_t)i10 * 4 + l);
            const __half2* vh = (const __half2*)&v;
            __half2 wh = __float2half2_rn(w.y);
            bl0 = __hfma2(vh[0], wh, bl0); bl1 = __hfma2(vh[1], wh, bl1);
            bl2 = __hfma2(vh[2], wh, bl2); bl3 = __hfma2(vh[3], wh, bl3);
        }
        {
            float4 v = __ldg(vt16 + (size_t)i01 * 4 + l);
            const __half2* vh = (const __half2*)&v;
            __half2 wh = __float2half2_rn(w.z);
            bl0 = __hfma2(vh[0], wh, bl0); bl1 = __hfma2(vh[1], wh, bl1);
            bl2 = __hfma2(vh[2], wh, bl2); bl3 = __hfma2(vh[3], wh, bl3);
        }
        {
            float4 v = __ldg(vt16 + (size_t)i11 * 4 + l);
            const __half2* vh = (const __half2*)&v;
            __half2 wh = __float2half2_rn(w.w);
            bl0 = __hfma2(vh[0], wh, bl0); bl1 = __hfma2(vh[1], wh, bl1);
            bl2 = __hfma2(vh[2], wh, bl2); bl3 = __hfma2(vh[3], wh, bl3);
        }

        float2 f0 = __half22float2(bl0);
        float2 f1 = __half22float2(bl1);
        float2 f2 = __half22float2(bl2);
        float2 f3 = __half22float2(bl3);
        fadd2(acc0, pack2(f0.x, f0.y));
        fadd2(acc1, pack2(f1.x, f1.y));
        fadd2(acc2v, pack2(f2.x, f2.y));
        fadd2(acc3, pack2(f3.x, f3.y));
    }

    if (valid) {
        float o0,o1,o2,o3,o4,o5,o6,o7;
        unpack2(acc0, o0, o1);
        unpack2(acc1, o2, o3);
        unpack2(acc2v, o4, o5);
        unpack2(acc3, o6, o7);
        float* op = out + ((size_t)b * LQ + q) * EMB + h * HD + 8 * l;
        *(float4*)(op)     = make_float4(o0, o1, o2, o3);
        *(float4*)(op + 4) = make_float4(o4, o5, o6, o7);
    }
}

// ================= launch =================
// Same DAG as the 170us baseline, but T nodes are INSERTED BEFORE P so the
// work distributor dispatches T's small churning blocks first and P backfills:
//   main: Ta -> (rec eTa) Tb -> (wait eP) Sb -> (wait eSa)
//   side: (wait eFork) P -> (rec eP) -> (wait eTa) Sa -> (rec eSa)
// (eFork is recorded before Ta, so P's only dependency is the fork point —
// identical dependencies, different insertion order.)
extern "C" void kernel_launch(void* const* d_in, const int* in_sizes, int n_in,
                              void* d_out, int out_size) {
    const float* query  = (const float*)d_in[0];
    const float* refpts = (const float*)d_in[1];
    const float* value  = (const float*)d_in[2];
    const float* W_off  = (const float*)d_in[4];
    const float* b_off  = (const float*)d_in[5];
    const float* W_attn = (const float*)d_in[6];
    const float* b_attn = (const float*)d_in[7];
    float* out = (float*)d_out;

    cudaStream_t s2;
    cudaEvent_t eFork, eTa, eP, eSa;
    cudaStreamCreateWithFlags(&s2, cudaStreamNonBlocking);
    cudaEventCreateWithFlags(&eFork, cudaEventDisableTiming);
    cudaEventCreateWithFlags(&eTa,   cudaEventDisableTiming);
    cudaEventCreateWithFlags(&eP,    cudaEventDisableTiming);
    cudaEventCreateWithFlags(&eSa,   cudaEventDisableTiming);

    const int NBH_HALF = (BS * NH) / 2;               // 128
    dim3 tgrid((TOTAL + 63) / 64, NBH_HALF);
    int swarps = NBH_HALF * QOCT;                     // 4864
    int sblocks = (swarps + 7) / 8;                   // 608

    // fork point (recorded BEFORE T so P's dep is still just the stream head)
    cudaEventRecord(eFork, 0);
    cudaStreamWaitEvent(s2, eFork, 0);

    // main: transpose halves enqueued FIRST (dispatch-order bias)
    k_transpose<<<tgrid, 256>>>(value, 0);
    cudaEventRecord(eTa, 0);
    k_transpose<<<tgrid, 256>>>(value, NBH_HALF);

    // side: proj enqueued after T (deps: fork point only)
    k_proj<<<MROWS / 32, 384, 0, s2>>>(query, refpts, W_off, b_off, W_attn, b_attn);
    cudaEventRecord(eP, s2);

    // side: sample first half (deps: P [program order] + Ta [event])
    cudaStreamWaitEvent(s2, eTa, 0);
    k_sample<<<sblocks, 256, 0, s2>>>(out, 0);
    cudaEventRecord(eSa, s2);

    // main: sample second half (deps: Tb [program order] + P [event])
    cudaStreamWaitEvent(0, eP, 0);
    k_sample<<<sblocks, 256>>>(out, NBH_HALF);

    // join side back into main so the captured graph is fully connected
    cudaStreamWaitEvent(0, eSa, 0);
}

// round 16
// speedup vs baseline: 2.2386x; 1.1488x over previous
#include <cuda_runtime.h>
#include <cuda_fp16.h>
#include <math.h>
#include <stdint.h>

// ---------------- problem constants ----------------
#define BS    32
#define LQ    300
#define NH    8
#define HD    32
#define EMB   (NH*HD)        // 256
#define NLVL  4
#define NPTS  4
#define SUMP  (NLVL*NPTS)    // 16
#define TOTAL 8500
#define MROWS (BS*LQ)        // 9600
#define NPOINT ((size_t)BS*NH*LQ*SUMP)   // 1,228,800

__device__ __constant__ int c_lvl_start[NLVL] = {0, 6400, 8000, 8400};
__device__ __constant__ int c_lvl_H[NLVL]     = {80, 40, 20, 10};
__device__ __constant__ int c_lvl_W[NLVL]     = {80, 40, 20, 10};

// ---------------- scratch ----------------
__device__ __half   g_valueT[(size_t)BS*NH*TOTAL*HD]; // ~139 MB, [b,h,s,d] fp16
__device__ ushort4  g_midx[NPOINT];                   // [bh][q][p] 4 clamped tap indices
__device__ float4   g_mw[NPOINT];                     // [bh][q][p] 4 attn-premult weights
#define WH_STRIDE 392
__device__ uint4    g_Wh4[(256 * WH_STRIDE) / 8];     // fp16 [W_off|W_attn], [256][392]

// ---------------- helpers ----------------
typedef unsigned long long ull;
__device__ __forceinline__ ull pack2(float lo, float hi) {
    ull r; asm("mov.b64 %0, {%1, %2};" : "=l"(r) : "f"(lo), "f"(hi)); return r;
}
__device__ __forceinline__ void unpack2(ull v, float& lo, float& hi) {
    asm("mov.b64 {%0, %1}, %2;" : "=f"(lo), "=f"(hi) : "l"(v));
}
__device__ __forceinline__ void fadd2(ull& d, ull a) {
    asm("add.rn.f32x2 %0, %0, %1;" : "+l"(d) : "l"(a));
}
__device__ __forceinline__ unsigned su32(const void* p) {
    unsigned a;
    asm("{ .reg .u64 t; cvta.to.shared.u64 t, %1; cvt.u32.u64 %0, t; }" : "=r"(a) : "l"(p));
    return a;
}
#define LDSM4(r, addr) \
    asm volatile("ldmatrix.sync.aligned.m8n8.x4.shared.b16 {%0,%1,%2,%3}, [%4];" \
        : "=r"((r)[0]), "=r"((r)[1]), "=r"((r)[2]), "=r"((r)[3]) : "r"(addr))
#define LDSM4T(rA, rB, addr) \
    asm volatile("ldmatrix.sync.aligned.m8n8.x4.trans.shared.b16 {%0,%1,%2,%3}, [%4];" \
        : "=r"((rA)[0]), "=r"((rA)[1]), "=r"((rB)[0]), "=r"((rB)[1]) : "r"(addr))
#define MMA16816(d, a, b) \
    asm volatile("mma.sync.aligned.m16n8k16.row.col.f32.f16.f16.f32 " \
        "{%0,%1,%2,%3}, {%4,%5,%6,%7}, {%8,%9}, {%0,%1,%2,%3};" \
        : "+f"((d)[0]), "+f"((d)[1]), "+f"((d)[2]), "+f"((d)[3]) \
        : "r"((a)[0]), "r"((a)[1]), "r"((a)[2]), "r"((a)[3]), "r"((b)[0]), "r"((b)[1]))

// ================= kernel 0: W fp32 -> fp16 (once) =================
__global__ __launch_bounds__(256) void k_wconv(const float* __restrict__ W_off,
                                               const float* __restrict__ W_attn) {
    int e = blockIdx.x * 256 + threadIdx.x;   // < 24576 (256 rows x 96 col-quads)
    if (e >= 256 * 96) return;
    int row  = e / 96;
    int cq   = e % 96;
    int col0 = cq * 4;
    const float* src = (col0 < 256) ? (W_off + row * 256 + col0)
                                    : (W_attn + row * 128 + (col0 - 256));
    float4 v = *(const float4*)src;
    __half2 h0 = __floats2half2_rn(v.x, v.y);
    __half2 h1 = __floats2half2_rn(v.z, v.w);
    uint2 pk;
    pk.x = *(unsigned*)&h0;
    pk.y = *(unsigned*)&h1;
    __half* Wh = (__half*)g_Wh4;
    *(uint2*)(Wh + row * WH_STRIDE + col0) = pk;
}

// ================= kernel 1: value transpose fp32 [b,h,d,s] -> fp16 [b,h,s,d] =================
__global__ __launch_bounds__(256) void k_transpose(const float* __restrict__ value, int bh0) {
    __shared__ float tile[32 * 68];
    int bh = bh0 + blockIdx.y;
    int s0 = blockIdx.x * 64;
    int t  = threadIdx.x;
    int sx4 = t & 15;
    int dh  = t >> 4;

    const float* src = value + (size_t)bh * HD * TOTAL;
    __half* dst = g_valueT + (size_t)bh * TOTAL * HD;

    int sbase = s0 + sx4 * 4;
    #pragma unroll
    for (int i = 0; i < 2; i++) {
        int d = dh + i * 16;
        float4 v;
        if (sbase + 3 < TOTAL) {
            v = *(const float4*)(src + (size_t)d * TOTAL + sbase);
        } else {
            v.x = (sbase + 0 < TOTAL) ? src[(size_t)d * TOTAL + sbase + 0] : 0.f;
            v.y = (sbase + 1 < TOTAL) ? src[(size_t)d * TOTAL + sbase + 1] : 0.f;
            v.z = (sbase + 2 < TOTAL) ? src[(size_t)d * TOTAL + sbase + 2] : 0.f;
            v.w = (sbase + 3 < TOTAL) ? src[(size_t)d * TOTAL + sbase + 3] : 0.f;
        }
        *(float4*)(tile + d * 68 + sx4 * 4) = v;
    }
    __syncthreads();
    #pragma unroll
    for (int i = 0; i < 4; i++) {
        int e  = t + i * 256;
        int r  = e >> 4;
        int dp = e & 15;
        int s  = s0 + r;
        if (s < TOTAL) {
            float lo = tile[(2*dp)     * 68 + r];
            float hi = tile[(2*dp + 1) * 68 + r];
            *((__half2*)(dst + (size_t)s * HD) + dp) = __floats2half2_rn(lo, hi);
        }
    }
}

// ================= kernel 2: tensor-core proj + softmax + tap meta =================
// Block = 32 rows, 256 threads (8 warps). Warp w computes rows 0..31 x cols w*48..+47
// via mma.m16n8k16 (fp16 in, fp32 acc). Epilogue = previous scalar code reading smem.
#define A_STRIDE   264      // halfs (528B, 33x16B -> ldmatrix conflict-free)
#define B_STRIDE   392      // halfs (784B, 49x16B -> conflict-free)
#define OUT_STRIDE 388      // floats (1552B)
#define OFF_A   0
#define OFF_B0  16896
#define OFF_B1  29440
#define OFF_OUT 41984
#define SMEM_PROJ (OFF_OUT + 32 * OUT_STRIDE * 4)   // 91,648 B

extern __shared__ char smp[];

__global__ __launch_bounds__(256) void k_proj_mma(const float* __restrict__ query,
                                                  const float* __restrict__ refpts,
                                                  const float* __restrict__ b_off,
                                                  const float* __restrict__ b_attn) {
    __half* aS     = (__half*)(smp + OFF_A);
    float*  outS   = (float*)(smp + OFF_OUT);
    float*  attn_s = (float*)(smp + OFF_B0);   // aliases B0 after the k-loop

    int m0   = blockIdx.x * 32;
    int t    = threadIdx.x;
    int lane = t & 31;
    int w    = t >> 5;

    // ---- load q block [32x256] fp32 -> fp16 aS ----
    {
        const float4* qsrc = (const float4*)(query + (size_t)m0 * EMB);
        #pragma unroll
        for (int j = 0; j < 8; j++) {
            int e   = t + j * 256;     // 0..2047
            int row = e >> 6;
            int c4  = e & 63;
            float4 v = qsrc[e];
            __half2 h0 = __floats2half2_rn(v.x, v.y);
            __half2 h1 = __floats2half2_rn(v.z, v.w);
            uint2 pk; pk.x = *(unsigned*)&h0; pk.y = *(unsigned*)&h1;
            *(uint2*)(aS + row * A_STRIDE + c4 * 4) = pk;
        }
    }
    // ---- per-thread chunk-copy offsets (3 x uint4 per chunk) ----
    const __half* Wh = (const __half*)g_Wh4;
    int idx0, idx1, idx2;
    {
        int e0 = t, e1 = t + 256, e2 = t + 512;
        idx0 = (e0 / 48) * B_STRIDE + (e0 % 48) * 8;
        idx1 = (e1 / 48) * B_STRIDE + (e1 % 48) * 8;
        idx2 = (e2 / 48) * B_STRIDE + (e2 % 48) * 8;
    }
    // ---- load chunk 0 -> B0 ----
    *(uint4*)(smp + OFF_B0 + idx0 * 2) = *(const uint4*)(Wh + idx0);
    *(uint4*)(smp + OFF_B0 + idx1 * 2) = *(const uint4*)(Wh + idx1);
    *(uint4*)(smp + OFF_B0 + idx2 * 2) = *(const uint4*)(Wh + idx2);
    __syncthreads();

    int n0 = w * 48;
    float d[2][6][4];
    #pragma unroll
    for (int mt = 0; mt < 2; mt++)
        #pragma unroll
        for (int nt = 0; nt < 6; nt++)
            #pragma unroll
            for (int c = 0; c < 4; c++) d[mt][nt][c] = 0.f;

    unsigned aAddrBase = su32(aS) + ((lane & 15) * A_STRIDE + (lane >> 4) * 8) * 2;
    unsigned bOff      = ((lane & 15) * B_STRIDE + n0 + (lane >> 4) * 8) * 2;
    unsigned b0u = su32(smp + OFF_B0);
    unsigned b1u = su32(smp + OFF_B1);

    for (int ch = 0; ch < 16; ch++) {
        uint4 st0, st1, st2;
        if (ch < 15) {
            int kb = (ch + 1) * 16 * B_STRIDE;
            st0 = *(const uint4*)(Wh + kb + idx0);
            st1 = *(const uint4*)(Wh + kb + idx1);
            st2 = *(const uint4*)(Wh + kb + idx2);
        }
        unsigned aA = aAddrBase + ch * 16 * 2;
        uint32_t a0[4], a1[4];
        LDSM4(a0, aA);
        LDSM4(a1, aA + 16 * A_STRIDE * 2);
        unsigned bA = ((ch & 1) ? b1u : b0u) + bOff;
        uint32_t bf[6][2];
        LDSM4T(bf[0], bf[1], bA);
        LDSM4T(bf[2], bf[3], bA + 32);
        LDSM4T(bf[4], bf[5], bA + 64);
        #pragma unroll
        for (int nt = 0; nt < 6; nt++) {
            MMA16816(d[0][nt], a0, bf[nt]);
            MMA16816(d[1][nt], a1, bf[nt]);
        }
        if (ch < 15) {
            char* dst = smp + ((ch & 1) ? OFF_B0 : OFF_B1);
            *(uint4*)(dst + idx0 * 2) = st0;
            *(uint4*)(dst + idx1 * 2) = st1;
            *(uint4*)(dst + idx2 * 2) = st2;
        }
        __syncthreads();
    }

    // ---- accs -> outS ----
    #pragma unroll
    for (int mt = 0; mt < 2; mt++)
        #pragma unroll
        for (int nt = 0; nt < 6; nt++) {
            int r  = mt * 16 + (lane >> 2);
            int cc = n0 + nt * 8 + (lane & 3) * 2;
            *(float2*)(outS + r * OUT_STRIDE + cc)       = make_float2(d[mt][nt][0], d[mt][nt][1]);
            *(float2*)(outS + (r + 8) * OUT_STRIDE + cc) = make_float2(d[mt][nt][2], d[mt][nt][3]);
        }
    __syncthreads();

    // ---- epilogue: 192 active threads; cq = col-quad 0..95, rg = row half ----
    int cq = t % 96;
    int rg = t / 96;            // 0,1 active; 2 idle
    bool active = (t < 192);
    bool is_off = (cq < 64);

    float bias_[4];
    if (active) {
        const float* bp = is_off ? (b_off + 4 * cq) : (b_attn + 4 * (cq - 64));
        float4 bb = *(const float4*)bp;
        bias_[0] = bb.x; bias_[1] = bb.y; bias_[2] = bb.z; bias_[3] = bb.w;
    }

    // phase A: attn -> softmax -> attn_s
    if (active && !is_off) {
        int cta = cq - 64;
        int h   = cta >> 2;
        int p0  = (4 * cta) & 15;
        for (int rr = 0; rr < 16; rr++) {
            int r = rg * 16 + rr;
            float4 v4 = *(const float4*)(outS + r * OUT_STRIDE + 4 * cq);
            float v[4] = {v4.x + bias_[0], v4.y + bias_[1], v4.z + bias_[2], v4.w + bias_[3]};
            float mx = fmaxf(fmaxf(v[0], v[1]), fmaxf(v[2], v[3]));
            mx = fmaxf(mx, __shfl_xor_sync(0xffffffffu, mx, 1));
            mx = fmaxf(mx, __shfl_xor_sync(0xffffffffu, mx, 2));
            float s = 0.f;
            #pragma unroll
            for (int c = 0; c < 4; c++) { v[c] = __expf(v[c] - mx); s += v[c]; }
            s += __shfl_xor_sync(0xffffffffu, s, 1);
            s += __shfl_xor_sync(0xffffffffu, s, 2);
            float inv = __frcp_rn(s);
            #pragma unroll
            for (int c = 0; c < 4; c++)
                attn_s[r * 128 + h * 16 + p0 + c] = v[c] * inv;
        }
    }
    __syncthreads();

    // phase B: off -> locations -> tap meta (attn-premultiplied)
    if (active && is_off) {
        int h     = cq >> 3;
        int pbase = (2 * cq) & 15;
        int lvl   = pbase >> 2;
        int Hh = c_lvl_H[lvl], Ww = c_lvl_W[lvl];
        int st = c_lvl_start[lvl];

        for (int rr = 0; rr < 16; rr++) {
            int r  = rg * 16 + rr;
            int gm = m0 + r;
            int b  = gm / LQ;
            int q  = gm - b * LQ;
            float4 rp = __ldg((const float4*)refpts + gm);
            float4 v4 = *(const float4*)(outS + r * OUT_STRIDE + 4 * cq);
            float vv[4] = {v4.x + bias_[0], v4.y + bias_[1], v4.z + bias_[2], v4.w + bias_[3]};
            size_t obase = ((size_t)(b * NH + h) * LQ + q) * SUMP + pbase;
            #pragma unroll
            for (int pt = 0; pt < 2; pt++) {
                float vx = vv[2 * pt];
                float vy = vv[2 * pt + 1];
                float locx = fmaf(vx * 0.125f, rp.z, rp.x);
                float locy = fmaf(vy * 0.125f, rp.w, rp.y);

                float x = locx * (float)Ww - 0.5f;
                float y = locy * (float)Hh - 0.5f;
                float fx0 = floorf(x), fy0 = floorf(y);
                int ix0 = (int)fx0, iy0 = (int)fy0;
                float fx = x - fx0, fy = y - fy0;
                int ix1 = ix0 + 1, iy1 = iy0 + 1;

                bool vx0 = (ix0 >= 0) & (ix0 < Ww);
                bool vx1 = (ix1 >= 0) & (ix1 < Ww);
                bool vy0 = (iy0 >= 0) & (iy0 < Hh);
                bool vy1 = (iy1 >= 0) & (iy1 < Hh);

                int cx0 = min(max(ix0, 0), Ww - 1);
                int cx1 = min(max(ix1, 0), Ww - 1);
                int cy0 = min(max(iy0, 0), Hh - 1);
                int cy1 = min(max(iy1, 0), Hh - 1);

                float a = attn_s[r * 128 + h * 16 + pbase + pt];

                ushort4 idx;
                idx.x = (unsigned short)(st + cy0 * Ww + cx0);
                idx.y = (unsigned short)(st + cy0 * Ww + cx1);
                idx.z = (unsigned short)(st + cy1 * Ww + cx0);
                idx.w = (unsigned short)(st + cy1 * Ww + cx1);

                float4 w4;
                w4.x = (vx0 & vy0) ? a * (1.f - fx) * (1.f - fy) : 0.f;
                w4.y = (vx1 & vy0) ? a * fx * (1.f - fy)         : 0.f;
                w4.z = (vx0 & vy1) ? a * (1.f - fx) * fy         : 0.f;
                w4.w = (vx1 & vy1) ? a * fx * fy                 : 0.f;

                g_midx[obase + pt] = idx;
                g_mw[obase + pt]   = w4;
            }
        }
    }
}

// ================= kernel 3: bilinear sampling + weighted sum =================
#define QOCT ((LQ + 7) / 8)   // 38
__global__ __launch_bounds__(256) void k_sample(float* __restrict__ out, int bh0) {
    int wq = blockIdx.x * 8 + (threadIdx.x >> 5);
    int lane = threadIdx.x & 31;
    int qi = lane >> 2;
    int l  = lane & 3;

    int oct = wq % QOCT;
    int bh  = bh0 + wq / QOCT;
    int q   = oct * 8 + qi;
    bool valid = (q < LQ);
    int qc = valid ? q : (LQ - 1);
    int b = bh >> 3;
    int h = bh & 7;

    size_t base = ((size_t)bh * LQ + qc) * SUMP;
    const uint2*  __restrict__ mi2 = (const uint2*)(g_midx + base);
    const float4* __restrict__ mw  = g_mw + base;
    const float4* __restrict__ vt16 =
        (const float4*)(g_valueT + (size_t)bh * TOTAL * HD);

    ull acc0 = 0ull, acc1 = 0ull, acc2v = 0ull, acc3 = 0ull;

    #pragma unroll
    for (int p = 0; p < SUMP; p++) {
        uint2  u = __ldg(mi2 + p);
        float4 w = __ldg(mw + p);
        int i00 = u.x & 0xFFFF;
        int i10 = u.x >> 16;
        int i01 = u.y & 0xFFFF;
        int i11 = u.y >> 16;

        __half2 z = __float2half2_rn(0.f);
        __half2 bl0 = z, bl1 = z, bl2 = z, bl3 = z;

        {
            float4 v = __ldg(vt16 + (size_t)i00 * 4 + l);
            const __half2* vh = (const __half2*)&v;
            __half2 wh = __float2half2_rn(w.x);
            bl0 = __hfma2(vh[0], wh, bl0); bl1 = __hfma2(vh[1], wh, bl1);
            bl2 = __hfma2(vh[2], wh, bl2); bl3 = __hfma2(vh[3], wh, bl3);
        }
        {
            float4 v = __ldg(vt16 + (size_t)i10 * 4 + l);
            const __half2* vh = (const __half2*)&v;
            __half2 wh = __float2half2_rn(w.y);
            bl0 = __hfma2(vh[0], wh, bl0); bl1 = __hfma2(vh[1], wh, bl1);
            bl2 = __hfma2(vh[2], wh, bl2); bl3 = __hfma2(vh[3], wh, bl3);
        }
        {
            float4 v = __ldg(vt16 + (size_t)i01 * 4 + l);
            const __half2* vh = (const __half2*)&v;
            __half2 wh = __float2half2_rn(w.z);
            bl0 = __hfma2(vh[0], wh, bl0); bl1 = __hfma2(vh[1], wh, bl1);
            bl2 = __hfma2(vh[2], wh, bl2); bl3 = __hfma2(vh[3], wh, bl3);
        }
        {
            float4 v = __ldg(vt16 + (size_t)i11 * 4 + l);
            const __half2* vh = (const __half2*)&v;
            __half2 wh = __float2half2_rn(w.w);
            bl0 = __hfma2(vh[0], wh, bl0); bl1 = __hfma2(vh[1], wh, bl1);
            bl2 = __hfma2(vh[2], wh, bl2); bl3 = __hfma2(vh[3], wh, bl3);
        }

        float2 f0 = __half22float2(bl0);
        float2 f1 = __half22float2(bl1);
        float2 f2 = __half22float2(bl2);
        float2 f3 = __half22float2(bl3);
        fadd2(acc0, pack2(f0.x, f0.y));
        fadd2(acc1, pack2(f1.x, f1.y));
        fadd2(acc2v, pack2(f2.x, f2.y));
        fadd2(acc3, pack2(f3.x, f3.y));
    }

    if (valid) {
        float o0,o1,o2,o3,o4,o5,o6,o7;
        unpack2(acc0, o0, o1);
        unpack2(acc1, o2, o3);
        unpack2(acc2v, o4, o5);
        unpack2(acc3, o6, o7);
        float* op = out + ((size_t)b * LQ + q) * EMB + h * HD + 8 * l;
        *(float4*)(op)     = make_float4(o0, o1, o2, o3);
        *(float4*)(op + 4) = make_float4(o4, o5, o6, o7);
    }
}

// ================= launch =================
// DAG (R14 ordering, T inserted first):
//   main: Ta -> (rec eTa) Tb -> (wait eP) Sb -> (wait eSa)
//   side: (wait eFork) Wconv -> Pmma -> (rec eP) -> (wait eTa) Sa -> (rec eSa)
extern "C" void kernel_launch(void* const* d_in, const int* in_sizes, int n_in,
                              void* d_out, int out_size) {
    const float* query  = (const float*)d_in[0];
    const float* refpts = (const float*)d_in[1];
    const float* value  = (const float*)d_in[2];
    const float* W_off  = (const float*)d_in[4];
    const float* b_off  = (const float*)d_in[5];
    const float* W_attn = (const float*)d_in[6];
    const float* b_attn = (const float*)d_in[7];
    float* out = (float*)d_out;

    cudaFuncSetAttribute(k_proj_mma, cudaFuncAttributeMaxDynamicSharedMemorySize, SMEM_PROJ);

    cudaStream_t s2;
    cudaEvent_t eFork, eTa, eP, eSa;
    cudaStreamCreateWithFlags(&s2, cudaStreamNonBlocking);
    cudaEventCreateWithFlags(&eFork, cudaEventDisableTiming);
    cudaEventCreateWithFlags(&eTa,   cudaEventDisableTiming);
    cudaEventCreateWithFlags(&eP,    cudaEventDisableTiming);
    cudaEventCreateWithFlags(&eSa,   cudaEventDisableTiming);

    const int NBH_HALF = (BS * NH) / 2;               // 128
    dim3 tgrid((TOTAL + 63) / 64, NBH_HALF);
    int swarps = NBH_HALF * QOCT;                     // 4864
    int sblocks = (swarps + 7) / 8;                   // 608

    cudaEventRecord(eFork, 0);
    cudaStreamWaitEvent(s2, eFork, 0);

    // main: transpose halves first (dispatch-order bias)
    k_transpose<<<tgrid, 256>>>(value, 0);
    cudaEventRecord(eTa, 0);
    k_transpose<<<tgrid, 256>>>(value, NBH_HALF);

    // side: W convert, then tensor-core proj
    k_wconv<<<96, 256, 0, s2>>>(W_off, W_attn);
    k_proj_mma<<<MROWS / 32, 256, SMEM_PROJ, s2>>>(query, refpts, b_off, b_attn);
    cudaEventRecord(eP, s2);

    // side: sample first half
    cudaStreamWaitEvent(s2, eTa, 0);
    k_sample<<<sblocks, 256, 0, s2>>>(out, 0);
    cudaEventRecord(eSa, s2);

    // main: sample second half
    cudaStreamWaitEvent(0, eP, 0);
    k_sample<<<sblocks, 256>>>(out, NBH_HALF);

    cudaStreamWaitEvent(0, eSa, 0);
}